// round 10
// baseline (speedup 1.0000x reference)
#include <cuda_runtime.h>
#include <cstdint>

#define HH  1024
#define BB  2
#define SS  2048
#define NHH 16
#define HDD 64
#define MT  (BB*SS)   // 4096

// ---------------- scratch globals (allocation-free) ----------------
__device__ __align__(128) float g_xhi[MT*HH];
__device__ __align__(128) float g_xlo[MT*HH];
__device__ __align__(128) float g_WdThi[HH*HH];   // (Wq-Wk)^T hi, tf32-rounded
__device__ __align__(128) float g_WdTlo[HH*HH];
__device__ __align__(128) float g_WvT[HH*HH];     // Wv^T tf32-rounded
__device__ __align__(128) float g_WoT[HH*HH];     // Wo^T tf32-rounded
__device__ __align__(128) float g_bd[HH];
__device__ __align__(128) float g_Dhi[MT*HH];     // tf32(D)
__device__ __align__(128) float g_Dlo[MT*HH];     // tf32(D - tf32(D))
__device__ __align__(128) float g_V[MT*HH];       // tf32-rounded V (bias incl.)
__device__ __align__(128) float g_C[MT*HH];       // tf32-rounded attention ctx

// ---------------- helpers ----------------
__device__ __forceinline__ float tfr(float x) {
    uint32_t r;
    asm("cvt.rna.tf32.f32 %0, %1;" : "=r"(r) : "f"(x));
    return __uint_as_float(r);
}
__device__ __forceinline__ void cp16(float* s, const float* g) {
    uint32_t sa = (uint32_t)__cvta_generic_to_shared(s);
    asm volatile("cp.async.cg.shared.global [%0], [%1], 16;" :: "r"(sa), "l"(g));
}
__device__ __forceinline__ void cp_commit() { asm volatile("cp.async.commit_group;"); }
template<int N> __device__ __forceinline__ void cp_wait() {
    asm volatile("cp.async.wait_group %0;" :: "n"(N));
}
__device__ __forceinline__ void mma8(float* d, const uint32_t* a, uint32_t b0, uint32_t b1) {
    asm volatile(
        "mma.sync.aligned.m16n8k8.row.col.f32.tf32.tf32.f32 "
        "{%0,%1,%2,%3},{%4,%5,%6,%7},{%8,%9},{%0,%1,%2,%3};"
        : "+f"(d[0]), "+f"(d[1]), "+f"(d[2]), "+f"(d[3])
        : "r"(a[0]), "r"(a[1]), "r"(a[2]), "r"(a[3]), "r"(b0), "r"(b1));
}

// ---------------- prep: x -> hi/lo planes; bd = bq-bk ----------------
__global__ void prep_x(const float* __restrict__ x,
                       const float* __restrict__ bq, const float* __restrict__ bk) {
    int i = blockIdx.x * 256 + threadIdx.x;
    float v = x[i];
    float hi = tfr(v);
    g_xhi[i] = hi;
    g_xlo[i] = tfr(v - hi);
    if (i < HH) g_bd[i] = bq[i] - bk[i];
}

// ---------------- prep: transpose + tf32-convert weights ----------------
__global__ void prep_w(const float* __restrict__ Wq, const float* __restrict__ Wk,
                       const float* __restrict__ Wv, const float* __restrict__ Wo) {
    __shared__ float t0[32][33];
    __shared__ float t1[32][33];
    const int z = blockIdx.z;
    const int c0 = blockIdx.x * 32, r0 = blockIdx.y * 32;
    const int tx = threadIdx.x & 31, ty = threadIdx.x >> 5;
    #pragma unroll
    for (int rr = ty; rr < 32; rr += 8) {
        int idx = (r0 + rr) * HH + c0 + tx;
        if (z == 0) {
            float v = Wq[idx] - Wk[idx];
            float hi = tfr(v);
            t0[rr][tx] = hi;
            t1[rr][tx] = tfr(v - hi);
        } else if (z == 1) t0[rr][tx] = tfr(Wv[idx]);
        else               t0[rr][tx] = tfr(Wo[idx]);
    }
    __syncthreads();
    #pragma unroll
    for (int rr = ty; rr < 32; rr += 8) {
        int odx = (c0 + rr) * HH + r0 + tx;   // transposed
        if (z == 0) { g_WdThi[odx] = t0[tx][rr]; g_WdTlo[odx] = t1[tx][rr]; }
        else if (z == 1) g_WvT[odx] = t0[tx][rr];
        else             g_WoT[odx] = t0[tx][rr];
    }
}

// ---------------- tf32 GEMM (plain): C = A @ BT^T + bias.  BK=8, 3-stage ----------------
#define GP 12
template<bool ROUND>
__global__ __launch_bounds__(256, 2) void gemm_plain(
    const float* __restrict__ A, const float* __restrict__ BT,
    const float* __restrict__ bias, float* __restrict__ C)
{
    extern __shared__ float sm[];
    const int K = HH, N = HH;
    const int tid = threadIdx.x, w = tid >> 5, lane = tid & 31;
    const int g = lane >> 2, t = lane & 3;
    const int wm = (w & 3) * 32, wn = (w >> 2) * 64;
    const int rowBase = blockIdx.y * 128, colBase = blockIdx.x * 128;
    const int lr = tid >> 1, lc = (tid & 1) * 4;

    const float* pA = A  + (size_t)(rowBase + lr) * K + lc;
    const float* pB = BT + (size_t)(colBase + lr) * K + lc;

    float acc[2][8][4];
    #pragma unroll
    for (int mt = 0; mt < 2; mt++)
        #pragma unroll
        for (int nt = 0; nt < 8; nt++)
            #pragma unroll
            for (int q = 0; q < 4; q++) acc[mt][nt][q] = 0.f;

    const int NIT = K / 8;
    const int off = lr * GP + lc;
    auto issue = [&](int it, int s) {
        float* base = sm + s * 2 * 128 * GP;
        cp16(base + off,          pA + it * 8);
        cp16(base + 128*GP + off, pB + it * 8);
    };
    issue(0, 0); cp_commit();
    issue(1, 1); cp_commit();

    for (int i = 0; i < NIT; i++) {
        cp_wait<1>();
        __syncthreads();
        const float* base = sm + (i % 3) * 2 * 128 * GP;
        const float* sA = base;
        const float* sB = base + 128 * GP;
        uint32_t a[2][4];
        #pragma unroll
        for (int mt = 0; mt < 2; mt++) {
            int r = wm + mt * 16 + g;
            a[mt][0] = __float_as_uint(sA[r * GP + t]);
            a[mt][1] = __float_as_uint(sA[(r + 8) * GP + t]);
            a[mt][2] = __float_as_uint(sA[r * GP + t + 4]);
            a[mt][3] = __float_as_uint(sA[(r + 8) * GP + t + 4]);
        }
        #pragma unroll
        for (int nt = 0; nt < 8; nt++) {
            int c = wn + nt * 8 + g;
            uint32_t b0 = __float_as_uint(sB[c * GP + t]);
            uint32_t b1 = __float_as_uint(sB[c * GP + t + 4]);
            mma8(acc[0][nt], a[0], b0, b1);
            mma8(acc[1][nt], a[1], b0, b1);
        }
        if (i + 2 < NIT) issue(i + 2, (i + 2) % 3);
        cp_commit();
    }

    #pragma unroll
    for (int mt = 0; mt < 2; mt++)
        #pragma unroll
        for (int nt = 0; nt < 8; nt++) {
            int row = rowBase + wm + mt * 16 + g;
            int col = colBase + wn + nt * 8 + 2 * t;
            float2 bb = *(const float2*)(bias + col);
            float v00 = acc[mt][nt][0] + bb.x, v01 = acc[mt][nt][1] + bb.y;
            float v10 = acc[mt][nt][2] + bb.x, v11 = acc[mt][nt][3] + bb.y;
            if (ROUND) { v00 = tfr(v00); v01 = tfr(v01); v10 = tfr(v10); v11 = tfr(v11); }
            *(float2*)(C + (size_t)row * N + col)       = make_float2(v00, v01);
            *(float2*)(C + (size_t)(row + 8) * N + col) = make_float2(v10, v11);
        }
}

// ---------------- tf32x2 split GEMM for D; writes hi/lo planes.  BK=8, 3-stage ----------------
__global__ __launch_bounds__(256, 2) void gemm_split(
    const float* __restrict__ Ah, const float* __restrict__ Al,
    const float* __restrict__ Bh, const float* __restrict__ Bl,
    const float* __restrict__ bias,
    float* __restrict__ Chi, float* __restrict__ Clo)
{
    extern __shared__ float sm[];
    const int K = HH, N = HH;
    const int tid = threadIdx.x, w = tid >> 5, lane = tid & 31;
    const int g = lane >> 2, t = lane & 3;
    const int wm = (w & 3) * 32, wn = (w >> 2) * 64;
    const int rowBase = blockIdx.y * 128, colBase = blockIdx.x * 128;
    const int lr = tid >> 1, lc = (tid & 1) * 4;

    const float* pAh = Ah + (size_t)(rowBase + lr) * K + lc;
    const float* pAl = Al + (size_t)(rowBase + lr) * K + lc;
    const float* pBh = Bh + (size_t)(colBase + lr) * K + lc;
    const float* pBl = Bl + (size_t)(colBase + lr) * K + lc;

    float acc[2][8][4];
    #pragma unroll
    for (int mt = 0; mt < 2; mt++)
        #pragma unroll
        for (int nt = 0; nt < 8; nt++)
            #pragma unroll
            for (int q = 0; q < 4; q++) acc[mt][nt][q] = 0.f;

    const int NIT = K / 8;
    const int off = lr * GP + lc;
    auto issue = [&](int it, int s) {
        float* base = sm + s * 4 * 128 * GP;
        cp16(base + off,            pAh + it * 8);
        cp16(base + 128*GP   + off, pAl + it * 8);
        cp16(base + 2*128*GP + off, pBh + it * 8);
        cp16(base + 3*128*GP + off, pBl + it * 8);
    };
    issue(0, 0); cp_commit();
    issue(1, 1); cp_commit();

    for (int i = 0; i < NIT; i++) {
        cp_wait<1>();
        __syncthreads();
        const float* base = sm + (i % 3) * 4 * 128 * GP;
        const float* sAh = base;
        const float* sAl = base + 128 * GP;
        const float* sBh = base + 2 * 128 * GP;
        const float* sBl = base + 3 * 128 * GP;
        uint32_t ah[2][4], al[2][4];
        #pragma unroll
        for (int mt = 0; mt < 2; mt++) {
            int r = wm + mt * 16 + g;
            ah[mt][0] = __float_as_uint(sAh[r * GP + t]);
            ah[mt][1] = __float_as_uint(sAh[(r + 8) * GP + t]);
            ah[mt][2] = __float_as_uint(sAh[r * GP + t + 4]);
            ah[mt][3] = __float_as_uint(sAh[(r + 8) * GP + t + 4]);
            al[mt][0] = __float_as_uint(sAl[r * GP + t]);
            al[mt][1] = __float_as_uint(sAl[(r + 8) * GP + t]);
            al[mt][2] = __float_as_uint(sAl[r * GP + t + 4]);
            al[mt][3] = __float_as_uint(sAl[(r + 8) * GP + t + 4]);
        }
        #pragma unroll
        for (int nt = 0; nt < 8; nt++) {
            int c = wn + nt * 8 + g;
            uint32_t bh0 = __float_as_uint(sBh[c * GP + t]);
            uint32_t bh1 = __float_as_uint(sBh[c * GP + t + 4]);
            uint32_t bl0 = __float_as_uint(sBl[c * GP + t]);
            uint32_t bl1 = __float_as_uint(sBl[c * GP + t + 4]);
            #pragma unroll
            for (int mt = 0; mt < 2; mt++) {
                mma8(acc[mt][nt], ah[mt], bh0, bh1);
                mma8(acc[mt][nt], ah[mt], bl0, bl1);
                mma8(acc[mt][nt], al[mt], bh0, bh1);
            }
        }
        if (i + 2 < NIT) issue(i + 2, (i + 2) % 3);
        cp_commit();
    }

    #pragma unroll
    for (int mt = 0; mt < 2; mt++)
        #pragma unroll
        for (int nt = 0; nt < 8; nt++) {
            int row = rowBase + wm + mt * 16 + g;
            int col = colBase + wn + nt * 8 + 2 * t;
            float2 bb = *(const float2*)(bias + col);
            float v00 = acc[mt][nt][0] + bb.x, v01 = acc[mt][nt][1] + bb.y;
            float v10 = acc[mt][nt][2] + bb.x, v11 = acc[mt][nt][3] + bb.y;
            float h00 = tfr(v00), h01 = tfr(v01), h10 = tfr(v10), h11 = tfr(v11);
            size_t r0 = (size_t)row * N, r1 = (size_t)(row + 8) * N;
            *(float2*)(Chi + r0 + col) = make_float2(h00, h01);
            *(float2*)(Chi + r1 + col) = make_float2(h10, h11);
            *(float2*)(Clo + r0 + col) = make_float2(tfr(v00 - h00), tfr(v01 - h01));
            *(float2*)(Clo + r1 + col) = make_float2(tfr(v10 - h10), tfr(v11 - h11));
        }
}

// ---------------- attention: 128-q rows, 256 threads, warp-owned rows ----------------
// 8 warps; warp w owns q-rows w*16..w*16+15 x ALL 64 j-cols. Score acc frags are
// permuted in-register (shfl) into PV A-frags: S never touches smem, no
// score->PV barrier. 1 barrier per j-tile (cp.async double buffer). Occ 2.
#define PK 68
#define PPV 72
#define ASTG (64*PK*2 + 64*PPV)      // 13312 floats per stage
__global__ __launch_bounds__(256, 2) void attn_mma() {
    extern __shared__ float sm[];
    const int tid = threadIdx.x, w = tid >> 5, lane = tid & 31;
    const int g = lane >> 2, t = lane & 3;
    const int mrow = w * 16;
    const int qt = blockIdx.x, bh = blockIdx.y;
    const int b = bh >> 4, h = bh & 15, q0 = qt * 128;

    const size_t base = (size_t)b * SS * HH + h * HDD;
    const float* Dh = g_Dhi + base;
    const float* Dl = g_Dlo + base;
    const float* Vp = g_V + base;

    // Dq hi/lo fragments resident in registers for the whole j-loop
    uint32_t qhi[8][4], qlo[8][4];
    {
        const size_t r0g = (size_t)(q0 + mrow + g) * HH;
        const size_t r1g = (size_t)(q0 + mrow + g + 8) * HH;
        #pragma unroll
        for (int c = 0; c < 8; c++) {
            int o = c * 8;
            qhi[c][0] = __float_as_uint(Dh[r0g + o + t]);
            qhi[c][1] = __float_as_uint(Dh[r1g + o + t]);
            qhi[c][2] = __float_as_uint(Dh[r0g + o + t + 4]);
            qhi[c][3] = __float_as_uint(Dh[r1g + o + t + 4]);
            qlo[c][0] = __float_as_uint(Dl[r0g + o + t]);
            qlo[c][1] = __float_as_uint(Dl[r1g + o + t]);
            qlo[c][2] = __float_as_uint(Dl[r0g + o + t + 4]);
            qlo[c][3] = __float_as_uint(Dl[r1g + o + t + 4]);
        }
    }

    float oacc[8][4];
    #pragma unroll
    for (int i = 0; i < 8; i++)
        #pragma unroll
        for (int j = 0; j < 4; j++) oacc[i][j] = 0.f;

    const int lr = tid >> 2, lc = (tid & 3) * 16;
    auto issue = [&](int jt, int s) {
        float* st = sm + s * ASTG;
        const float* srcH = Dh + (size_t)(jt * 64 + lr) * HH + lc;
        const float* srcL = Dl + (size_t)(jt * 64 + lr) * HH + lc;
        const float* srcV = Vp + (size_t)(jt * 64 + lr) * HH + lc;
        #pragma unroll
        for (int u = 0; u < 16; u += 4) {
            cp16(st + lr * PK + lc + u,             srcH + u);
            cp16(st + 64*PK + lr * PK + lc + u,     srcL + u);
            cp16(st + 2*64*PK + lr * PPV + lc + u,  srcV + u);
        }
    };

    const int r0 = q0 + mrow + g;
    const int srcl1 = (lane & ~3) | (t >> 1);   // 4g + (t>>1)
    const int srcl2 = srcl1 + 2;
    const bool odd = (t & 1) != 0;

    const int jt0 = 2 * qt;
    int buf = 0;
    issue(jt0, 0); cp_commit();
    for (int jt = jt0; jt < SS / 64; jt++) {
        cp_wait<0>();
        __syncthreads();   // stage ready; all warps done with peer buffer
        if (jt + 1 < SS / 64) { issue(jt + 1, buf ^ 1); }
        cp_commit();
        const float* st  = sm + buf * ASTG;
        const float* sKh = st;
        const float* sKl = st + 64 * PK;
        const float* sV  = st + 2 * 64 * PK;
        const int j0 = jt * 64;

        #pragma unroll
        for (int nt = 0; nt < 8; nt++) {
            // score block: 16 rows x 8 cols (j = j0 + nt*8 ..), tf32x2 3-mma
            float sacc[4] = {0.f, 0.f, 0.f, 0.f};
            const int jr = (nt * 8 + g) * PK;
            #pragma unroll
            for (int c = 0; c < 8; c++) {
                int o = c * 8;
                uint32_t bh0 = __float_as_uint(sKh[jr + o + t]);
                uint32_t bh1 = __float_as_uint(sKh[jr + o + t + 4]);
                uint32_t bl0 = __float_as_uint(sKl[jr + o + t]);
                uint32_t bl1 = __float_as_uint(sKl[jr + o + t + 4]);
                mma8(sacc, qhi[c], bh0, bh1);
                mma8(sacc, qhi[c], bl0, bl1);
                mma8(sacc, qlo[c], bh0, bh1);
            }

            // mask (strict upper) + exp + tf32 pre-round
            const int colb = j0 + nt * 8 + 2 * t;
            float s0 = (colb     > r0    ) ? tfr(__expf(-0.5f * sacc[0])) : 0.f;
            float s1 = (colb + 1 > r0    ) ? tfr(__expf(-0.5f * sacc[1])) : 0.f;
            float s2 = (colb     > r0 + 8) ? tfr(__expf(-0.5f * sacc[2])) : 0.f;
            float s3 = (colb + 1 > r0 + 8) ? tfr(__expf(-0.5f * sacc[3])) : 0.f;

            // permute acc frag (row g, col 2t|2t+1) -> A frag (col t, t+4) via shfl
            float x0 = __shfl_sync(0xffffffffu, s0, srcl1);
            float x1 = __shfl_sync(0xffffffffu, s1, srcl1);
            float x2 = __shfl_sync(0xffffffffu, s2, srcl1);
            float x3 = __shfl_sync(0xffffffffu, s3, srcl1);
            float y0 = __shfl_sync(0xffffffffu, s0, srcl2);
            float y1 = __shfl_sync(0xffffffffu, s1, srcl2);
            float y2 = __shfl_sync(0xffffffffu, s2, srcl2);
            float y3 = __shfl_sync(0xffffffffu, s3, srcl2);
            uint32_t a[4];
            a[0] = __float_as_uint(odd ? x1 : x0);   // S[g][t]
            a[1] = __float_as_uint(odd ? x3 : x2);   // S[g+8][t]
            a[2] = __float_as_uint(odd ? y1 : y0);   // S[g][t+4]
            a[3] = __float_as_uint(odd ? y3 : y2);   // S[g+8][t+4]

            // PV for k-chunk nt: update all 8 d-blocks (k ascending => same order)
            const int kb = nt * 8;
            #pragma unroll
            for (int dt = 0; dt < 8; dt++) {
                int dbc = dt * 8;
                uint32_t b0 = __float_as_uint(sV[(kb + t) * PPV + dbc + g]);
                uint32_t b1 = __float_as_uint(sV[(kb + t + 4) * PPV + dbc + g]);
                mma8(oacc[dt], a, b0, b1);
            }
        }
        buf ^= 1;
    }

    // write ctx pre-rounded (O GEMM consumes tf32 directly)
    float* Cb = g_C + base;
    #pragma unroll
    for (int dt = 0; dt < 8; dt++) {
        int col = dt * 8 + 2 * t;
        *(float2*)(Cb + (size_t)(q0 + mrow + g) * HH + col) =
            make_float2(tfr(oacc[dt][0]), tfr(oacc[dt][1]));
        *(float2*)(Cb + (size_t)(q0 + mrow + g + 8) * HH + col) =
            make_float2(tfr(oacc[dt][2]), tfr(oacc[dt][3]));
    }
}

// ---------------------------------------------------------------------------
extern "C" void kernel_launch(void* const* d_in, const int* in_sizes, int n_in,
                              void* d_out, int out_size) {
    const float* x  = (const float*)d_in[0];
    const float* Wq = (const float*)d_in[1];
    const float* bq = (const float*)d_in[2];
    const float* Wk = (const float*)d_in[3];
    const float* bk = (const float*)d_in[4];
    const float* Wv = (const float*)d_in[5];
    const float* bv = (const float*)d_in[6];
    const float* Wo = (const float*)d_in[7];
    const float* bo = (const float*)d_in[8];
    float* out = (float*)d_out;

    float *pxhi, *pxlo, *pWdThi, *pWdTlo, *pWvT, *pWoT, *pbd, *pDhi, *pDlo, *pV, *pC;
    cudaGetSymbolAddress((void**)&pxhi, g_xhi);
    cudaGetSymbolAddress((void**)&pxlo, g_xlo);
    cudaGetSymbolAddress((void**)&pWdThi, g_WdThi);
    cudaGetSymbolAddress((void**)&pWdTlo, g_WdTlo);
    cudaGetSymbolAddress((void**)&pWvT, g_WvT);
    cudaGetSymbolAddress((void**)&pWoT, g_WoT);
    cudaGetSymbolAddress((void**)&pbd, g_bd);
    cudaGetSymbolAddress((void**)&pDhi, g_Dhi);
    cudaGetSymbolAddress((void**)&pDlo, g_Dlo);
    cudaGetSymbolAddress((void**)&pV, g_V);
    cudaGetSymbolAddress((void**)&pC, g_C);

    const int smem_plain = 3 * 2 * 128 * GP * sizeof(float);   // 36864
    const int smem_split = 3 * 4 * 128 * GP * sizeof(float);   // 73728
    const int smem_attn  = 2 * ASTG * sizeof(float);           // 106496
    static bool attr_set = false;
    if (!attr_set) {
        cudaFuncSetAttribute(gemm_split, cudaFuncAttributeMaxDynamicSharedMemorySize, smem_split);
        cudaFuncSetAttribute(gemm_plain<true>,  cudaFuncAttributeMaxDynamicSharedMemorySize, smem_plain);
        cudaFuncSetAttribute(gemm_plain<false>, cudaFuncAttributeMaxDynamicSharedMemorySize, smem_plain);
        cudaFuncSetAttribute(attn_mma, cudaFuncAttributeMaxDynamicSharedMemorySize, smem_attn);
        attr_set = true;
    }

    prep_x<<<MT*HH/256, 256>>>(x, bq, bk);
    prep_w<<<dim3(32, 32, 3), 256>>>(Wq, Wk, Wv, Wo);

    dim3 gg(HH/128, MT/128);  // (8, 32)
    gemm_split<<<gg, 256, smem_split>>>(pxhi, pxlo, pWdThi, pWdTlo, pbd, pDhi, pDlo);
    gemm_plain<true><<<gg, 256, smem_plain>>>(pxhi, pWvT, bv, pV);

    attn_mma<<<dim3(SS/128, BB*NHH), 256, smem_attn>>>();

    gemm_plain<false><<<gg, 256, smem_plain>>>(pC, pWoT, bo, out);
}

// round 12
// speedup vs baseline: 1.0886x; 1.0886x over previous
#include <cuda_runtime.h>
#include <cstdint>

#define HH  1024
#define BB  2
#define SS  2048
#define NHH 16
#define HDD 64
#define MT  (BB*SS)   // 4096

// ---------------- scratch globals (allocation-free) ----------------
__device__ __align__(128) float g_xhi[MT*HH];
__device__ __align__(128) float g_xlo[MT*HH];
__device__ __align__(128) float g_WdThi[HH*HH];   // (Wq-Wk)^T hi, tf32-rounded
__device__ __align__(128) float g_WdTlo[HH*HH];
__device__ __align__(128) float g_WvT[HH*HH];     // Wv^T tf32-rounded
__device__ __align__(128) float g_WoT[HH*HH];     // Wo^T tf32-rounded
__device__ __align__(128) float g_bd[HH];
__device__ __align__(128) float g_Dhi[MT*HH];     // tf32(D)
__device__ __align__(128) float g_Dlo[MT*HH];     // tf32(D - tf32(D))
__device__ __align__(128) float g_V[MT*HH];       // tf32-rounded V (bias incl.)
__device__ __align__(128) float g_C[MT*HH];       // tf32-rounded attention ctx

// ---------------- helpers ----------------
__device__ __forceinline__ float tfr(float x) {
    uint32_t r;
    asm("cvt.rna.tf32.f32 %0, %1;" : "=r"(r) : "f"(x));
    return __uint_as_float(r);
}
__device__ __forceinline__ void cp16(float* s, const float* g) {
    uint32_t sa = (uint32_t)__cvta_generic_to_shared(s);
    asm volatile("cp.async.cg.shared.global [%0], [%1], 16;" :: "r"(sa), "l"(g));
}
__device__ __forceinline__ void cp_commit() { asm volatile("cp.async.commit_group;"); }
template<int N> __device__ __forceinline__ void cp_wait() {
    asm volatile("cp.async.wait_group %0;" :: "n"(N));
}
__device__ __forceinline__ void mma8(float* d, const uint32_t* a, uint32_t b0, uint32_t b1) {
    asm volatile(
        "mma.sync.aligned.m16n8k8.row.col.f32.tf32.tf32.f32 "
        "{%0,%1,%2,%3},{%4,%5,%6,%7},{%8,%9},{%0,%1,%2,%3};"
        : "+f"(d[0]), "+f"(d[1]), "+f"(d[2]), "+f"(d[3])
        : "r"(a[0]), "r"(a[1]), "r"(a[2]), "r"(a[3]), "r"(b0), "r"(b1));
}

// ---------------- prep: x -> hi/lo planes; bd = bq-bk ----------------
__global__ void prep_x(const float* __restrict__ x,
                       const float* __restrict__ bq, const float* __restrict__ bk) {
    int i = blockIdx.x * 256 + threadIdx.x;
    float v = x[i];
    float hi = tfr(v);
    g_xhi[i] = hi;
    g_xlo[i] = tfr(v - hi);
    if (i < HH) g_bd[i] = bq[i] - bk[i];
}

// ---------------- prep: transpose + tf32-convert weights ----------------
__global__ void prep_w(const float* __restrict__ Wq, const float* __restrict__ Wk,
                       const float* __restrict__ Wv, const float* __restrict__ Wo) {
    __shared__ float t0[32][33];
    __shared__ float t1[32][33];
    const int z = blockIdx.z;
    const int c0 = blockIdx.x * 32, r0 = blockIdx.y * 32;
    const int tx = threadIdx.x & 31, ty = threadIdx.x >> 5;
    #pragma unroll
    for (int rr = ty; rr < 32; rr += 8) {
        int idx = (r0 + rr) * HH + c0 + tx;
        if (z == 0) {
            float v = Wq[idx] - Wk[idx];
            float hi = tfr(v);
            t0[rr][tx] = hi;
            t1[rr][tx] = tfr(v - hi);
        } else if (z == 1) t0[rr][tx] = tfr(Wv[idx]);
        else               t0[rr][tx] = tfr(Wo[idx]);
    }
    __syncthreads();
    #pragma unroll
    for (int rr = ty; rr < 32; rr += 8) {
        int odx = (c0 + rr) * HH + r0 + tx;   // transposed
        if (z == 0) { g_WdThi[odx] = t0[tx][rr]; g_WdTlo[odx] = t1[tx][rr]; }
        else if (z == 1) g_WvT[odx] = t0[tx][rr];
        else             g_WoT[odx] = t0[tx][rr];
    }
}

// ---------------- tf32 GEMM (plain): C = A @ BT^T + bias.  BK=8, 3-stage ----------------
#define GP 12
template<bool ROUND>
__global__ __launch_bounds__(256, 2) void gemm_plain(
    const float* __restrict__ A, const float* __restrict__ BT,
    const float* __restrict__ bias, float* __restrict__ C)
{
    extern __shared__ float sm[];
    const int K = HH, N = HH;
    const int tid = threadIdx.x, w = tid >> 5, lane = tid & 31;
    const int g = lane >> 2, t = lane & 3;
    const int wm = (w & 3) * 32, wn = (w >> 2) * 64;
    const int rowBase = blockIdx.y * 128, colBase = blockIdx.x * 128;
    const int lr = tid >> 1, lc = (tid & 1) * 4;

    const float* pA = A  + (size_t)(rowBase + lr) * K + lc;
    const float* pB = BT + (size_t)(colBase + lr) * K + lc;

    float acc[2][8][4];
    #pragma unroll
    for (int mt = 0; mt < 2; mt++)
        #pragma unroll
        for (int nt = 0; nt < 8; nt++)
            #pragma unroll
            for (int q = 0; q < 4; q++) acc[mt][nt][q] = 0.f;

    const int NIT = K / 8;
    const int off = lr * GP + lc;
    auto issue = [&](int it, int s) {
        float* base = sm + s * 2 * 128 * GP;
        cp16(base + off,          pA + it * 8);
        cp16(base + 128*GP + off, pB + it * 8);
    };
    issue(0, 0); cp_commit();
    issue(1, 1); cp_commit();

    for (int i = 0; i < NIT; i++) {
        cp_wait<1>();
        __syncthreads();
        const float* base = sm + (i % 3) * 2 * 128 * GP;
        const float* sA = base;
        const float* sB = base + 128 * GP;
        uint32_t a[2][4];
        #pragma unroll
        for (int mt = 0; mt < 2; mt++) {
            int r = wm + mt * 16 + g;
            a[mt][0] = __float_as_uint(sA[r * GP + t]);
            a[mt][1] = __float_as_uint(sA[(r + 8) * GP + t]);
            a[mt][2] = __float_as_uint(sA[r * GP + t + 4]);
            a[mt][3] = __float_as_uint(sA[(r + 8) * GP + t + 4]);
        }
        #pragma unroll
        for (int nt = 0; nt < 8; nt++) {
            int c = wn + nt * 8 + g;
            uint32_t b0 = __float_as_uint(sB[c * GP + t]);
            uint32_t b1 = __float_as_uint(sB[c * GP + t + 4]);
            mma8(acc[0][nt], a[0], b0, b1);
            mma8(acc[1][nt], a[1], b0, b1);
        }
        if (i + 2 < NIT) issue(i + 2, (i + 2) % 3);
        cp_commit();
    }

    #pragma unroll
    for (int mt = 0; mt < 2; mt++)
        #pragma unroll
        for (int nt = 0; nt < 8; nt++) {
            int row = rowBase + wm + mt * 16 + g;
            int col = colBase + wn + nt * 8 + 2 * t;
            float2 bb = *(const float2*)(bias + col);
            float v00 = acc[mt][nt][0] + bb.x, v01 = acc[mt][nt][1] + bb.y;
            float v10 = acc[mt][nt][2] + bb.x, v11 = acc[mt][nt][3] + bb.y;
            if (ROUND) { v00 = tfr(v00); v01 = tfr(v01); v10 = tfr(v10); v11 = tfr(v11); }
            *(float2*)(C + (size_t)row * N + col)       = make_float2(v00, v01);
            *(float2*)(C + (size_t)(row + 8) * N + col) = make_float2(v10, v11);
        }
}

// ---------------- tf32x2 split GEMM for D; writes hi/lo planes.  BK=8, 3-stage ----------------
__global__ __launch_bounds__(256, 2) void gemm_split(
    const float* __restrict__ Ah, const float* __restrict__ Al,
    const float* __restrict__ Bh, const float* __restrict__ Bl,
    const float* __restrict__ bias,
    float* __restrict__ Chi, float* __restrict__ Clo)
{
    extern __shared__ float sm[];
    const int K = HH, N = HH;
    const int tid = threadIdx.x, w = tid >> 5, lane = tid & 31;
    const int g = lane >> 2, t = lane & 3;
    const int wm = (w & 3) * 32, wn = (w >> 2) * 64;
    const int rowBase = blockIdx.y * 128, colBase = blockIdx.x * 128;
    const int lr = tid >> 1, lc = (tid & 1) * 4;

    const float* pAh = Ah + (size_t)(rowBase + lr) * K + lc;
    const float* pAl = Al + (size_t)(rowBase + lr) * K + lc;
    const float* pBh = Bh + (size_t)(colBase + lr) * K + lc;
    const float* pBl = Bl + (size_t)(colBase + lr) * K + lc;

    float acc[2][8][4];
    #pragma unroll
    for (int mt = 0; mt < 2; mt++)
        #pragma unroll
        for (int nt = 0; nt < 8; nt++)
            #pragma unroll
            for (int q = 0; q < 4; q++) acc[mt][nt][q] = 0.f;

    const int NIT = K / 8;
    const int off = lr * GP + lc;
    auto issue = [&](int it, int s) {
        float* base = sm + s * 4 * 128 * GP;
        cp16(base + off,            pAh + it * 8);
        cp16(base + 128*GP   + off, pAl + it * 8);
        cp16(base + 2*128*GP + off, pBh + it * 8);
        cp16(base + 3*128*GP + off, pBl + it * 8);
    };
    issue(0, 0); cp_commit();
    issue(1, 1); cp_commit();

    for (int i = 0; i < NIT; i++) {
        cp_wait<1>();
        __syncthreads();
        const float* base = sm + (i % 3) * 4 * 128 * GP;
        const float* sAh = base;
        const float* sAl = base + 128 * GP;
        const float* sBh = base + 2 * 128 * GP;
        const float* sBl = base + 3 * 128 * GP;
        uint32_t ah[2][4], al[2][4];
        #pragma unroll
        for (int mt = 0; mt < 2; mt++) {
            int r = wm + mt * 16 + g;
            ah[mt][0] = __float_as_uint(sAh[r * GP + t]);
            ah[mt][1] = __float_as_uint(sAh[(r + 8) * GP + t]);
            ah[mt][2] = __float_as_uint(sAh[r * GP + t + 4]);
            ah[mt][3] = __float_as_uint(sAh[(r + 8) * GP + t + 4]);
            al[mt][0] = __float_as_uint(sAl[r * GP + t]);
            al[mt][1] = __float_as_uint(sAl[(r + 8) * GP + t]);
            al[mt][2] = __float_as_uint(sAl[r * GP + t + 4]);
            al[mt][3] = __float_as_uint(sAl[(r + 8) * GP + t + 4]);
        }
        #pragma unroll
        for (int nt = 0; nt < 8; nt++) {
            int c = wn + nt * 8 + g;
            uint32_t bh0 = __float_as_uint(sBh[c * GP + t]);
            uint32_t bh1 = __float_as_uint(sBh[c * GP + t + 4]);
            uint32_t bl0 = __float_as_uint(sBl[c * GP + t]);
            uint32_t bl1 = __float_as_uint(sBl[c * GP + t + 4]);
            #pragma unroll
            for (int mt = 0; mt < 2; mt++) {
                mma8(acc[mt][nt], ah[mt], bh0, bh1);
                mma8(acc[mt][nt], ah[mt], bl0, bl1);
                mma8(acc[mt][nt], al[mt], bh0, bh1);
            }
        }
        if (i + 2 < NIT) issue(i + 2, (i + 2) % 3);
        cp_commit();
    }

    #pragma unroll
    for (int mt = 0; mt < 2; mt++)
        #pragma unroll
        for (int nt = 0; nt < 8; nt++) {
            int row = rowBase + wm + mt * 16 + g;
            int col = colBase + wn + nt * 8 + 2 * t;
            float2 bb = *(const float2*)(bias + col);
            float v00 = acc[mt][nt][0] + bb.x, v01 = acc[mt][nt][1] + bb.y;
            float v10 = acc[mt][nt][2] + bb.x, v11 = acc[mt][nt][3] + bb.y;
            float h00 = tfr(v00), h01 = tfr(v01), h10 = tfr(v10), h11 = tfr(v11);
            size_t r0 = (size_t)row * N, r1 = (size_t)(row + 8) * N;
            *(float2*)(Chi + r0 + col) = make_float2(h00, h01);
            *(float2*)(Chi + r1 + col) = make_float2(h10, h11);
            *(float2*)(Clo + r0 + col) = make_float2(tfr(v00 - h00), tfr(v01 - h01));
            *(float2*)(Clo + r1 + col) = make_float2(tfr(v10 - h10), tfr(v11 - h11));
        }
}

// ---------------- attention: 128-q rows, 512 threads ----------------
// warp w: rows (w&7)*16, cols (w>>3)*32. Dq hi AND lo fragments in registers
// (no persistent smem tile). S in its own smem region. 1 full barrier per
// j-tile (buffer swap) + 1 pairwise NAMED barrier (warps w, w^8 share S rows).
#define PK 68
#define PPV 72
#define ASTG (64*PK*2 + 64*PPV)      // 13312 floats per stage
#define SOFF (2*ASTG)                // S tile (128*PK)
__global__ __launch_bounds__(512, 1) void attn_mma() {
    extern __shared__ float sm[];
    const int tid = threadIdx.x, w = tid >> 5, lane = tid & 31;
    const int g = lane >> 2, t = lane & 3;
    const int mrow = (w & 7) * 16, ncol = (w >> 3) * 32;
    const int barid = 1 + (w & 7);      // named barrier per row-pair (ids 1..8)
    const int qt = blockIdx.x, bh = blockIdx.y;
    const int b = bh >> 4, h = bh & 15, q0 = qt * 128;

    const size_t base = (size_t)b * SS * HH + h * HDD;
    const float* Dh = g_Dhi + base;
    const float* Dl = g_Dlo + base;
    const float* Vp = g_V + base;
    float* sS = sm + SOFF;

    // Dq hi/lo fragments resident in registers for the whole j-loop
    uint32_t qhi[8][4], qlo[8][4];
    {
        const size_t r0g = (size_t)(q0 + mrow + g) * HH;
        const size_t r1g = (size_t)(q0 + mrow + g + 8) * HH;
        #pragma unroll
        for (int c = 0; c < 8; c++) {
            int o = c * 8;
            qhi[c][0] = __float_as_uint(Dh[r0g + o + t]);
            qhi[c][1] = __float_as_uint(Dh[r1g + o + t]);
            qhi[c][2] = __float_as_uint(Dh[r0g + o + t + 4]);
            qhi[c][3] = __float_as_uint(Dh[r1g + o + t + 4]);
            qlo[c][0] = __float_as_uint(Dl[r0g + o + t]);
            qlo[c][1] = __float_as_uint(Dl[r1g + o + t]);
            qlo[c][2] = __float_as_uint(Dl[r0g + o + t + 4]);
            qlo[c][3] = __float_as_uint(Dl[r1g + o + t + 4]);
        }
    }

    float oacc[4][4];
    #pragma unroll
    for (int i = 0; i < 4; i++)
        #pragma unroll
        for (int j = 0; j < 4; j++) oacc[i][j] = 0.f;

    const int lr = tid >> 3, lc8 = (tid & 7) * 8;
    auto issue = [&](int jt, int s) {
        float* st = sm + s * ASTG;
        const float* srcH = Dh + (size_t)(jt * 64 + lr) * HH + lc8;
        const float* srcL = Dl + (size_t)(jt * 64 + lr) * HH + lc8;
        const float* srcV = Vp + (size_t)(jt * 64 + lr) * HH + lc8;
        cp16(st + lr * PK + lc8,                srcH);
        cp16(st + lr * PK + lc8 + 4,            srcH + 4);
        cp16(st + 64*PK + lr * PK + lc8,        srcL);
        cp16(st + 64*PK + lr * PK + lc8 + 4,    srcL + 4);
        cp16(st + 2*64*PK + lr * PPV + lc8,     srcV);
        cp16(st + 2*64*PK + lr * PPV + lc8 + 4, srcV + 4);
    };

    const int jt0 = 2 * qt;
    int buf = 0;
    issue(jt0, 0); cp_commit();
    for (int jt = jt0; jt < SS / 64; jt++) {
        cp_wait<0>();
        __syncthreads();   // stage ready; all warps past prev PV (S + peer buf free)
        if (jt + 1 < SS / 64) { issue(jt + 1, buf ^ 1); }
        cp_commit();
        const float* st  = sm + buf * ASTG;
        const float* sKh = st;
        const float* sKl = st + 64 * PK;
        const float* sV  = st + 2 * 64 * PK;
        const int j0 = jt * 64;

        // score = Dq@Dk^T (3-mma tf32x2)
        float sacc[4][4];
        #pragma unroll
        for (int i = 0; i < 4; i++)
            #pragma unroll
            for (int j = 0; j < 4; j++) sacc[i][j] = 0.f;

        #pragma unroll
        for (int c = 0; c < 8; c++) {
            int o = c * 8;
            #pragma unroll
            for (int nt = 0; nt < 4; nt++) {
                int jr = (ncol + nt * 8 + g) * PK;
                uint32_t bh0 = __float_as_uint(sKh[jr + o + t]);
                uint32_t bh1 = __float_as_uint(sKh[jr + o + t + 4]);
                uint32_t bl0 = __float_as_uint(sKl[jr + o + t]);
                uint32_t bl1 = __float_as_uint(sKl[jr + o + t + 4]);
                mma8(sacc[nt], qhi[c], bh0, bh1);
                mma8(sacc[nt], qhi[c], bl0, bl1);
                mma8(sacc[nt], qlo[c], bh0, bh1);
            }
        }

        // mask (strict upper) + exp + pre-round, write S (own region, own rows)
        const int r0 = q0 + mrow + g;
        #pragma unroll
        for (int nt = 0; nt < 4; nt++) {
            int colb = j0 + ncol + nt * 8 + 2 * t;
            float s0 = (colb     > r0    ) ? tfr(__expf(-0.5f * sacc[nt][0])) : 0.f;
            float s1 = (colb + 1 > r0    ) ? tfr(__expf(-0.5f * sacc[nt][1])) : 0.f;
            float s2 = (colb     > r0 + 8) ? tfr(__expf(-0.5f * sacc[nt][2])) : 0.f;
            float s3 = (colb + 1 > r0 + 8) ? tfr(__expf(-0.5f * sacc[nt][3])) : 0.f;
            int cb = ncol + nt * 8 + 2 * t;
            *(float2*)&sS[(mrow + g) * PK + cb]     = make_float2(s0, s1);
            *(float2*)&sS[(mrow + g + 8) * PK + cb] = make_float2(s2, s3);
        }
        // pairwise sync: only warps w and w^8 share these S rows
        asm volatile("bar.sync %0, 64;" :: "r"(barid) : "memory");

        // PV: oacc += S @ V  (plain tf32)
        #pragma unroll
        for (int c = 0; c < 8; c++) {
            int k = c * 8;
            uint32_t a[4];
            a[0] = __float_as_uint(sS[(mrow + g) * PK + k + t]);
            a[1] = __float_as_uint(sS[(mrow + g + 8) * PK + k + t]);
            a[2] = __float_as_uint(sS[(mrow + g) * PK + k + t + 4]);
            a[3] = __float_as_uint(sS[(mrow + g + 8) * PK + k + t + 4]);
            #pragma unroll
            for (int nt = 0; nt < 4; nt++) {
                int dbc = ncol + nt * 8;
                uint32_t b0 = __float_as_uint(sV[(k + t) * PPV + dbc + g]);
                uint32_t b1 = __float_as_uint(sV[(k + t + 4) * PPV + dbc + g]);
                mma8(oacc[nt], a, b0, b1);
            }
        }
        buf ^= 1;
    }

    // write ctx pre-rounded (O GEMM consumes tf32 directly)
    float* Cb = g_C + base;
    #pragma unroll
    for (int nt = 0; nt < 4; nt++) {
        int col = ncol + nt * 8 + 2 * t;
        *(float2*)(Cb + (size_t)(q0 + mrow + g) * HH + col) =
            make_float2(tfr(oacc[nt][0]), tfr(oacc[nt][1]));
        *(float2*)(Cb + (size_t)(q0 + mrow + g + 8) * HH + col) =
            make_float2(tfr(oacc[nt][2]), tfr(oacc[nt][3]));
    }
}

// ---------------------------------------------------------------------------
extern "C" void kernel_launch(void* const* d_in, const int* in_sizes, int n_in,
                              void* d_out, int out_size) {
    const float* x  = (const float*)d_in[0];
    const float* Wq = (const float*)d_in[1];
    const float* bq = (const float*)d_in[2];
    const float* Wk = (const float*)d_in[3];
    const float* bk = (const float*)d_in[4];
    const float* Wv = (const float*)d_in[5];
    const float* bv = (const float*)d_in[6];
    const float* Wo = (const float*)d_in[7];
    const float* bo = (const float*)d_in[8];
    float* out = (float*)d_out;

    float *pxhi, *pxlo, *pWdThi, *pWdTlo, *pWvT, *pWoT, *pbd, *pDhi, *pDlo, *pV, *pC;
    cudaGetSymbolAddress((void**)&pxhi, g_xhi);
    cudaGetSymbolAddress((void**)&pxlo, g_xlo);
    cudaGetSymbolAddress((void**)&pWdThi, g_WdThi);
    cudaGetSymbolAddress((void**)&pWdTlo, g_WdTlo);
    cudaGetSymbolAddress((void**)&pWvT, g_WvT);
    cudaGetSymbolAddress((void**)&pWoT, g_WoT);
    cudaGetSymbolAddress((void**)&pbd, g_bd);
    cudaGetSymbolAddress((void**)&pDhi, g_Dhi);
    cudaGetSymbolAddress((void**)&pDlo, g_Dlo);
    cudaGetSymbolAddress((void**)&pV, g_V);
    cudaGetSymbolAddress((void**)&pC, g_C);

    const int smem_plain = 3 * 2 * 128 * GP * sizeof(float);          // 36864
    const int smem_split = 3 * 4 * 128 * GP * sizeof(float);          // 73728
    const int smem_attn  = (2 * ASTG + 128 * PK) * sizeof(float);     // 141312
    static bool attr_set = false;
    if (!attr_set) {
        cudaFuncSetAttribute(gemm_split, cudaFuncAttributeMaxDynamicSharedMemorySize, smem_split);
        cudaFuncSetAttribute(gemm_plain<true>,  cudaFuncAttributeMaxDynamicSharedMemorySize, smem_plain);
        cudaFuncSetAttribute(gemm_plain<false>, cudaFuncAttributeMaxDynamicSharedMemorySize, smem_plain);
        cudaFuncSetAttribute(attn_mma, cudaFuncAttributeMaxDynamicSharedMemorySize, smem_attn);
        attr_set = true;
    }

    prep_x<<<MT*HH/256, 256>>>(x, bq, bk);
    prep_w<<<dim3(32, 32, 3), 256>>>(Wq, Wk, Wv, Wo);

    dim3 gg(HH/128, MT/128);  // (8, 32)
    gemm_split<<<gg, 256, smem_split>>>(pxhi, pxlo, pWdThi, pWdTlo, pbd, pDhi, pDlo);
    gemm_plain<true><<<gg, 256, smem_plain>>>(pxhi, pWvT, bv, pV);

    attn_mma<<<dim3(SS/128, BB*NHH), 512, smem_attn>>>();

    gemm_plain<false><<<gg, 256, smem_plain>>>(pC, pWoT, bo, out);
}

// round 14
// speedup vs baseline: 1.0929x; 1.0040x over previous
#include <cuda_runtime.h>
#include <cstdint>

#define HH  1024
#define BB  2
#define SS  2048
#define NHH 16
#define HDD 64
#define MT  (BB*SS)   // 4096

// ---------------- scratch globals (allocation-free) ----------------
__device__ __align__(128) float g_xhi[MT*HH];
__device__ __align__(128) float g_xlo[MT*HH];
__device__ __align__(128) float g_WdThi[HH*HH];   // (Wq-Wk)^T hi, tf32-rounded
__device__ __align__(128) float g_WdTlo[HH*HH];
__device__ __align__(128) float g_WvT[HH*HH];     // Wv^T tf32-rounded
__device__ __align__(128) float g_WoT[HH*HH];     // Wo^T tf32-rounded
__device__ __align__(128) float g_bd[HH];
__device__ __align__(128) float g_Dhi[MT*HH];     // tf32(D)
__device__ __align__(128) float g_Dlo[MT*HH];     // tf32(D - tf32(D))
__device__ __align__(128) float g_V[MT*HH];       // tf32-rounded V (bias incl.)
__device__ __align__(128) float g_C[MT*HH];       // tf32-rounded attention ctx

// ---------------- helpers ----------------
__device__ __forceinline__ float tfr(float x) {
    uint32_t r;
    asm("cvt.rna.tf32.f32 %0, %1;" : "=r"(r) : "f"(x));
    return __uint_as_float(r);
}
__device__ __forceinline__ void cp16(float* s, const float* g) {
    uint32_t sa = (uint32_t)__cvta_generic_to_shared(s);
    asm volatile("cp.async.cg.shared.global [%0], [%1], 16;" :: "r"(sa), "l"(g));
}
__device__ __forceinline__ void cp_commit() { asm volatile("cp.async.commit_group;"); }
template<int N> __device__ __forceinline__ void cp_wait() {
    asm volatile("cp.async.wait_group %0;" :: "n"(N));
}
__device__ __forceinline__ void mma8(float* d, const uint32_t* a, uint32_t b0, uint32_t b1) {
    asm volatile(
        "mma.sync.aligned.m16n8k8.row.col.f32.tf32.tf32.f32 "
        "{%0,%1,%2,%3},{%4,%5,%6,%7},{%8,%9},{%0,%1,%2,%3};"
        : "+f"(d[0]), "+f"(d[1]), "+f"(d[2]), "+f"(d[3])
        : "r"(a[0]), "r"(a[1]), "r"(a[2]), "r"(a[3]), "r"(b0), "r"(b1));
}
// mbarrier helpers (acquire waits; arrive has release.cta semantics)
__device__ __forceinline__ void mb_init(uint32_t addr, uint32_t cnt) {
    asm volatile("mbarrier.init.shared.b64 [%0], %1;" :: "r"(addr), "r"(cnt) : "memory");
}
__device__ __forceinline__ void mb_arrive(uint32_t addr) {
    asm volatile("mbarrier.arrive.shared.b64 _, [%0];" :: "r"(addr) : "memory");
}
__device__ __forceinline__ void cp_arrive(uint32_t addr) {
    asm volatile("cp.async.mbarrier.arrive.noinc.shared::cta.b64 [%0];" :: "r"(addr) : "memory");
}
__device__ __forceinline__ void mb_wait(uint32_t addr, uint32_t parity) {
    uint32_t done;
    asm volatile(
        "{\n\t.reg .pred p;\n\t"
        "mbarrier.try_wait.parity.acquire.cta.shared::cta.b64 p, [%1], %2;\n\t"
        "selp.b32 %0, 1, 0, p;\n\t}"
        : "=r"(done) : "r"(addr), "r"(parity) : "memory");
    if (!done) {
        asm volatile(
            "{\n\t.reg .pred P1;\n\t"
            "WAIT_LOOP_%=:\n\t"
            "mbarrier.try_wait.parity.acquire.cta.shared::cta.b64 P1, [%0], %1, 0x989680;\n\t"
            "@P1 bra.uni WAIT_DONE_%=;\n\t"
            "bra.uni WAIT_LOOP_%=;\n\t"
            "WAIT_DONE_%=:\n\t}"
            :: "r"(addr), "r"(parity) : "memory");
    }
}

// ---------------- prep: x -> hi/lo planes; bd = bq-bk ----------------
__global__ void prep_x(const float* __restrict__ x,
                       const float* __restrict__ bq, const float* __restrict__ bk) {
    int i = blockIdx.x * 256 + threadIdx.x;
    float v = x[i];
    float hi = tfr(v);
    g_xhi[i] = hi;
    g_xlo[i] = tfr(v - hi);
    if (i < HH) g_bd[i] = bq[i] - bk[i];
}

// ---------------- prep: transpose + tf32-convert weights ----------------
__global__ void prep_w(const float* __restrict__ Wq, const float* __restrict__ Wk,
                       const float* __restrict__ Wv, const float* __restrict__ Wo) {
    __shared__ float t0[32][33];
    __shared__ float t1[32][33];
    const int z = blockIdx.z;
    const int c0 = blockIdx.x * 32, r0 = blockIdx.y * 32;
    const int tx = threadIdx.x & 31, ty = threadIdx.x >> 5;
    #pragma unroll
    for (int rr = ty; rr < 32; rr += 8) {
        int idx = (r0 + rr) * HH + c0 + tx;
        if (z == 0) {
            float v = Wq[idx] - Wk[idx];
            float hi = tfr(v);
            t0[rr][tx] = hi;
            t1[rr][tx] = tfr(v - hi);
        } else if (z == 1) t0[rr][tx] = tfr(Wv[idx]);
        else               t0[rr][tx] = tfr(Wo[idx]);
    }
    __syncthreads();
    #pragma unroll
    for (int rr = ty; rr < 32; rr += 8) {
        int odx = (c0 + rr) * HH + r0 + tx;   // transposed
        if (z == 0) { g_WdThi[odx] = t0[tx][rr]; g_WdTlo[odx] = t1[tx][rr]; }
        else if (z == 1) g_WvT[odx] = t0[tx][rr];
        else             g_WoT[odx] = t0[tx][rr];
    }
}

// ---------------- tf32 GEMM (plain): C = A @ BT^T + bias.  BK=8, 3-stage ----------------
#define GP 12
template<bool ROUND>
__global__ __launch_bounds__(256, 2) void gemm_plain(
    const float* __restrict__ A, const float* __restrict__ BT,
    const float* __restrict__ bias, float* __restrict__ C)
{
    extern __shared__ float sm[];
    const int K = HH, N = HH;
    const int tid = threadIdx.x, w = tid >> 5, lane = tid & 31;
    const int g = lane >> 2, t = lane & 3;
    const int wm = (w & 3) * 32, wn = (w >> 2) * 64;
    const int rowBase = blockIdx.y * 128, colBase = blockIdx.x * 128;
    const int lr = tid >> 1, lc = (tid & 1) * 4;

    const float* pA = A  + (size_t)(rowBase + lr) * K + lc;
    const float* pB = BT + (size_t)(colBase + lr) * K + lc;

    float acc[2][8][4];
    #pragma unroll
    for (int mt = 0; mt < 2; mt++)
        #pragma unroll
        for (int nt = 0; nt < 8; nt++)
            #pragma unroll
            for (int q = 0; q < 4; q++) acc[mt][nt][q] = 0.f;

    const int NIT = K / 8;
    const int off = lr * GP + lc;
    auto issue = [&](int it, int s) {
        float* base = sm + s * 2 * 128 * GP;
        cp16(base + off,          pA + it * 8);
        cp16(base + 128*GP + off, pB + it * 8);
    };
    issue(0, 0); cp_commit();
    issue(1, 1); cp_commit();

    for (int i = 0; i < NIT; i++) {
        cp_wait<1>();
        __syncthreads();
        const float* base = sm + (i % 3) * 2 * 128 * GP;
        const float* sA = base;
        const float* sB = base + 128 * GP;
        uint32_t a[2][4];
        #pragma unroll
        for (int mt = 0; mt < 2; mt++) {
            int r = wm + mt * 16 + g;
            a[mt][0] = __float_as_uint(sA[r * GP + t]);
            a[mt][1] = __float_as_uint(sA[(r + 8) * GP + t]);
            a[mt][2] = __float_as_uint(sA[r * GP + t + 4]);
            a[mt][3] = __float_as_uint(sA[(r + 8) * GP + t + 4]);
        }
        #pragma unroll
        for (int nt = 0; nt < 8; nt++) {
            int c = wn + nt * 8 + g;
            uint32_t b0 = __float_as_uint(sB[c * GP + t]);
            uint32_t b1 = __float_as_uint(sB[c * GP + t + 4]);
            mma8(acc[0][nt], a[0], b0, b1);
            mma8(acc[1][nt], a[1], b0, b1);
        }
        if (i + 2 < NIT) issue(i + 2, (i + 2) % 3);
        cp_commit();
    }

    #pragma unroll
    for (int mt = 0; mt < 2; mt++)
        #pragma unroll
        for (int nt = 0; nt < 8; nt++) {
            int row = rowBase + wm + mt * 16 + g;
            int col = colBase + wn + nt * 8 + 2 * t;
            float2 bb = *(const float2*)(bias + col);
            float v00 = acc[mt][nt][0] + bb.x, v01 = acc[mt][nt][1] + bb.y;
            float v10 = acc[mt][nt][2] + bb.x, v11 = acc[mt][nt][3] + bb.y;
            if (ROUND) { v00 = tfr(v00); v01 = tfr(v01); v10 = tfr(v10); v11 = tfr(v11); }
            *(float2*)(C + (size_t)row * N + col)       = make_float2(v00, v01);
            *(float2*)(C + (size_t)(row + 8) * N + col) = make_float2(v10, v11);
        }
}

// ---------------- tf32x2 split GEMM for D; writes hi/lo planes.  BK=8, 3-stage ----------------
__global__ __launch_bounds__(256, 2) void gemm_split(
    const float* __restrict__ Ah, const float* __restrict__ Al,
    const float* __restrict__ Bh, const float* __restrict__ Bl,
    const float* __restrict__ bias,
    float* __restrict__ Chi, float* __restrict__ Clo)
{
    extern __shared__ float sm[];
    const int K = HH, N = HH;
    const int tid = threadIdx.x, w = tid >> 5, lane = tid & 31;
    const int g = lane >> 2, t = lane & 3;
    const int wm = (w & 3) * 32, wn = (w >> 2) * 64;
    const int rowBase = blockIdx.y * 128, colBase = blockIdx.x * 128;
    const int lr = tid >> 1, lc = (tid & 1) * 4;

    const float* pAh = Ah + (size_t)(rowBase + lr) * K + lc;
    const float* pAl = Al + (size_t)(rowBase + lr) * K + lc;
    const float* pBh = Bh + (size_t)(colBase + lr) * K + lc;
    const float* pBl = Bl + (size_t)(colBase + lr) * K + lc;

    float acc[2][8][4];
    #pragma unroll
    for (int mt = 0; mt < 2; mt++)
        #pragma unroll
        for (int nt = 0; nt < 8; nt++)
            #pragma unroll
            for (int q = 0; q < 4; q++) acc[mt][nt][q] = 0.f;

    const int NIT = K / 8;
    const int off = lr * GP + lc;
    auto issue = [&](int it, int s) {
        float* base = sm + s * 4 * 128 * GP;
        cp16(base + off,            pAh + it * 8);
        cp16(base + 128*GP   + off, pAl + it * 8);
        cp16(base + 2*128*GP + off, pBh + it * 8);
        cp16(base + 3*128*GP + off, pBl + it * 8);
    };
    issue(0, 0); cp_commit();
    issue(1, 1); cp_commit();

    for (int i = 0; i < NIT; i++) {
        cp_wait<1>();
        __syncthreads();
        const float* base = sm + (i % 3) * 4 * 128 * GP;
        const float* sAh = base;
        const float* sAl = base + 128 * GP;
        const float* sBh = base + 2 * 128 * GP;
        const float* sBl = base + 3 * 128 * GP;
        uint32_t ah[2][4], al[2][4];
        #pragma unroll
        for (int mt = 0; mt < 2; mt++) {
            int r = wm + mt * 16 + g;
            ah[mt][0] = __float_as_uint(sAh[r * GP + t]);
            ah[mt][1] = __float_as_uint(sAh[(r + 8) * GP + t]);
            ah[mt][2] = __float_as_uint(sAh[r * GP + t + 4]);
            ah[mt][3] = __float_as_uint(sAh[(r + 8) * GP + t + 4]);
            al[mt][0] = __float_as_uint(sAl[r * GP + t]);
            al[mt][1] = __float_as_uint(sAl[(r + 8) * GP + t]);
            al[mt][2] = __float_as_uint(sAl[r * GP + t + 4]);
            al[mt][3] = __float_as_uint(sAl[(r + 8) * GP + t + 4]);
        }
        #pragma unroll
        for (int nt = 0; nt < 8; nt++) {
            int c = wn + nt * 8 + g;
            uint32_t bh0 = __float_as_uint(sBh[c * GP + t]);
            uint32_t bh1 = __float_as_uint(sBh[c * GP + t + 4]);
            uint32_t bl0 = __float_as_uint(sBl[c * GP + t]);
            uint32_t bl1 = __float_as_uint(sBl[c * GP + t + 4]);
            #pragma unroll
            for (int mt = 0; mt < 2; mt++) {
                mma8(acc[mt][nt], ah[mt], bh0, bh1);
                mma8(acc[mt][nt], ah[mt], bl0, bl1);
                mma8(acc[mt][nt], al[mt], bh0, bh1);
            }
        }
        if (i + 2 < NIT) issue(i + 2, (i + 2) % 3);
        cp_commit();
    }

    #pragma unroll
    for (int mt = 0; mt < 2; mt++)
        #pragma unroll
        for (int nt = 0; nt < 8; nt++) {
            int row = rowBase + wm + mt * 16 + g;
            int col = colBase + wn + nt * 8 + 2 * t;
            float2 bb = *(const float2*)(bias + col);
            float v00 = acc[mt][nt][0] + bb.x, v01 = acc[mt][nt][1] + bb.y;
            float v10 = acc[mt][nt][2] + bb.x, v11 = acc[mt][nt][3] + bb.y;
            float h00 = tfr(v00), h01 = tfr(v01), h10 = tfr(v10), h11 = tfr(v11);
            size_t r0 = (size_t)row * N, r1 = (size_t)(row + 8) * N;
            *(float2*)(Chi + r0 + col) = make_float2(h00, h01);
            *(float2*)(Chi + r1 + col) = make_float2(h10, h11);
            *(float2*)(Clo + r0 + col) = make_float2(tfr(v00 - h00), tfr(v01 - h01));
            *(float2*)(Clo + r1 + col) = make_float2(tfr(v10 - h10), tfr(v11 - h11));
        }
}

// ---------------- attention: 128-q rows, 512 threads, mbarrier pipeline ----------------
// warp w: rows (w&7)*16, cols (w>>3)*32. Dq hi/lo in registers. 3-stage cp.async
// ring synced by mbarriers (full/empty, count 512) — NO full __syncthreads in the
// j-loop, warps may skew by one j-tile. S protected by pairwise bar.sync (w, w^8).
#define PK 68
#define PPV 72
#define ASTG (64*PK*2 + 64*PPV)      // 13312 floats per stage
#define SOFF (3*ASTG)                // S tile (128*PK floats)
#define MBOFF (SOFF + 128*PK)        // mbarriers: full[3] then empty[3], 8B each
__global__ __launch_bounds__(512, 1) void attn_mma() {
    extern __shared__ float sm[];
    const int tid = threadIdx.x, w = tid >> 5, lane = tid & 31;
    const int g = lane >> 2, t = lane & 3;
    const int mrow = (w & 7) * 16, ncol = (w >> 3) * 32;
    const int barid = 1 + (w & 7);      // named barrier per row-pair (ids 1..8)
    const int qt = blockIdx.x, bh = blockIdx.y;
    const int b = bh >> 4, h = bh & 15, q0 = qt * 128;

    const size_t base = (size_t)b * SS * HH + h * HDD;
    const float* Dh = g_Dhi + base;
    const float* Dl = g_Dlo + base;
    const float* Vp = g_V + base;
    float* sS = sm + SOFF;
    const uint32_t mb = (uint32_t)__cvta_generic_to_shared(sm) + MBOFF * 4;
    // full[s] at mb + s*8 ; empty[s] at mb + 24 + s*8

    if (tid == 0) {
        #pragma unroll
        for (int s2 = 0; s2 < 3; s2++) {
            mb_init(mb + s2 * 8, 512);
            mb_init(mb + 24 + s2 * 8, 512);
        }
    }

    // Dq hi/lo fragments resident in registers for the whole j-loop
    uint32_t qhi[8][4], qlo[8][4];
    {
        const size_t r0g = (size_t)(q0 + mrow + g) * HH;
        const size_t r1g = (size_t)(q0 + mrow + g + 8) * HH;
        #pragma unroll
        for (int c = 0; c < 8; c++) {
            int o = c * 8;
            qhi[c][0] = __float_as_uint(Dh[r0g + o + t]);
            qhi[c][1] = __float_as_uint(Dh[r1g + o + t]);
            qhi[c][2] = __float_as_uint(Dh[r0g + o + t + 4]);
            qhi[c][3] = __float_as_uint(Dh[r1g + o + t + 4]);
            qlo[c][0] = __float_as_uint(Dl[r0g + o + t]);
            qlo[c][1] = __float_as_uint(Dl[r1g + o + t]);
            qlo[c][2] = __float_as_uint(Dl[r0g + o + t + 4]);
            qlo[c][3] = __float_as_uint(Dl[r1g + o + t + 4]);
        }
    }

    float oacc[4][4];
    #pragma unroll
    for (int i = 0; i < 4; i++)
        #pragma unroll
        for (int j = 0; j < 4; j++) oacc[i][j] = 0.f;

    const int lr = tid >> 3, lc8 = (tid & 7) * 8;
    auto issue = [&](int jt, int s) {
        float* st = sm + s * ASTG;
        const float* srcH = Dh + (size_t)(jt * 64 + lr) * HH + lc8;
        const float* srcL = Dl + (size_t)(jt * 64 + lr) * HH + lc8;
        const float* srcV = Vp + (size_t)(jt * 64 + lr) * HH + lc8;
        cp16(st + lr * PK + lc8,                srcH);
        cp16(st + lr * PK + lc8 + 4,            srcH + 4);
        cp16(st + 64*PK + lr * PK + lc8,        srcL);
        cp16(st + 64*PK + lr * PK + lc8 + 4,    srcL + 4);
        cp16(st + 2*64*PK + lr * PPV + lc8,     srcV);
        cp16(st + 2*64*PK + lr * PPV + lc8 + 4, srcV + 4);
    };

    __syncthreads();   // mbarrier init visible before any arrive

    const int jt0 = 2 * qt;
    const int NJ = SS / 64 - jt0;   // >= 2

    // prologue: fill up to 3 stages
    #pragma unroll
    for (int p = 0; p < 3; p++) {
        if (p < NJ) {
            issue(jt0 + p, p);
            cp_arrive(mb + p * 8);
        }
    }

    for (int idx = 0; idx < NJ; idx++) {
        const int s = idx % 3;
        mb_wait(mb + s * 8, (uint32_t)((idx / 3) & 1));   // stage data ready

        // reload stage consumed at idx-1 with tile idx+2 (skew tolerance: 1 tile)
        if (idx >= 1 && idx + 2 < NJ) {
            const int ls = (idx + 2) % 3;                 // == (idx-1)%3
            mb_wait(mb + 24 + ls * 8, (uint32_t)(((idx - 1) / 3) & 1));
            issue(jt0 + idx + 2, ls);
            cp_arrive(mb + ls * 8);
        }

        const float* st  = sm + s * ASTG;
        const float* sKh = st;
        const float* sKl = st + 64 * PK;
        const float* sV  = st + 2 * 64 * PK;
        const int j0 = (jt0 + idx) * 64;

        // score = Dq@Dk^T (3-mma tf32x2)
        float sacc[4][4];
        #pragma unroll
        for (int i = 0; i < 4; i++)
            #pragma unroll
            for (int j = 0; j < 4; j++) sacc[i][j] = 0.f;

        #pragma unroll
        for (int c = 0; c < 8; c++) {
            int o = c * 8;
            #pragma unroll
            for (int nt = 0; nt < 4; nt++) {
                int jr = (ncol + nt * 8 + g) * PK;
                uint32_t bh0 = __float_as_uint(sKh[jr + o + t]);
                uint32_t bh1 = __float_as_uint(sKh[jr + o + t + 4]);
                uint32_t bl0 = __float_as_uint(sKl[jr + o + t]);
                uint32_t bl1 = __float_as_uint(sKl[jr + o + t + 4]);
                mma8(sacc[nt], qhi[c], bh0, bh1);
                mma8(sacc[nt], qhi[c], bl0, bl1);
                mma8(sacc[nt], qlo[c], bh0, bh1);
            }
        }

        // mask (strict upper) + exp + pre-round, write S (pair-owned rows)
        const int r0 = q0 + mrow + g;
        #pragma unroll
        for (int nt = 0; nt < 4; nt++) {
            int colb = j0 + ncol + nt * 8 + 2 * t;
            float s0 = (colb     > r0    ) ? tfr(__expf(-0.5f * sacc[nt][0])) : 0.f;
            float s1 = (colb + 1 > r0    ) ? tfr(__expf(-0.5f * sacc[nt][1])) : 0.f;
            float s2 = (colb     > r0 + 8) ? tfr(__expf(-0.5f * sacc[nt][2])) : 0.f;
            float s3 = (colb + 1 > r0 + 8) ? tfr(__expf(-0.5f * sacc[nt][3])) : 0.f;
            int cb = ncol + nt * 8 + 2 * t;
            *(float2*)&sS[(mrow + g) * PK + cb]     = make_float2(s0, s1);
            *(float2*)&sS[(mrow + g + 8) * PK + cb] = make_float2(s2, s3);
        }
        // pairwise sync: warps w and w^8 share these S rows
        asm volatile("bar.sync %0, 64;" :: "r"(barid) : "memory");

        // PV: oacc += S @ V  (plain tf32)
        #pragma unroll
        for (int c = 0; c < 8; c++) {
            int k = c * 8;
            uint32_t a[4];
            a[0] = __float_as_uint(sS[(mrow + g) * PK + k + t]);
            a[1] = __float_as_uint(sS[(mrow + g + 8) * PK + k + t]);
            a[2] = __float_as_uint(sS[(mrow + g) * PK + k + t + 4]);
            a[3] = __float_as_uint(sS[(mrow + g + 8) * PK + k + t + 4]);
            #pragma unroll
            for (int nt = 0; nt < 4; nt++) {
                int dbc = ncol + nt * 8;
                uint32_t b0 = __float_as_uint(sV[(k + t) * PPV + dbc + g]);
                uint32_t b1 = __float_as_uint(sV[(k + t + 4) * PPV + dbc + g]);
                mma8(oacc[nt], a, b0, b1);
            }
        }
        // pairwise sync: partner's PV reads of S done before next iter's S writes
        asm volatile("bar.sync %0, 64;" :: "r"(barid) : "memory");
        // release stage s (all reads above ordered before arrive: release.cta)
        mb_arrive(mb + 24 + s * 8);
    }

    // write ctx pre-rounded (O GEMM consumes tf32 directly)
    float* Cb = g_C + base;
    #pragma unroll
    for (int nt = 0; nt < 4; nt++) {
        int col = ncol + nt * 8 + 2 * t;
        *(float2*)(Cb + (size_t)(q0 + mrow + g) * HH + col) =
            make_float2(tfr(oacc[nt][0]), tfr(oacc[nt][1]));
        *(float2*)(Cb + (size_t)(q0 + mrow + g + 8) * HH + col) =
            make_float2(tfr(oacc[nt][2]), tfr(oacc[nt][3]));
    }
}

// ---------------------------------------------------------------------------
extern "C" void kernel_launch(void* const* d_in, const int* in_sizes, int n_in,
                              void* d_out, int out_size) {
    const float* x  = (const float*)d_in[0];
    const float* Wq = (const float*)d_in[1];
    const float* bq = (const float*)d_in[2];
    const float* Wk = (const float*)d_in[3];
    const float* bk = (const float*)d_in[4];
    const float* Wv = (const float*)d_in[5];
    const float* bv = (const float*)d_in[6];
    const float* Wo = (const float*)d_in[7];
    const float* bo = (const float*)d_in[8];
    float* out = (float*)d_out;

    float *pxhi, *pxlo, *pWdThi, *pWdTlo, *pWvT, *pWoT, *pbd, *pDhi, *pDlo, *pV, *pC;
    cudaGetSymbolAddress((void**)&pxhi, g_xhi);
    cudaGetSymbolAddress((void**)&pxlo, g_xlo);
    cudaGetSymbolAddress((void**)&pWdThi, g_WdThi);
    cudaGetSymbolAddress((void**)&pWdTlo, g_WdTlo);
    cudaGetSymbolAddress((void**)&pWvT, g_WvT);
    cudaGetSymbolAddress((void**)&pWoT, g_WoT);
    cudaGetSymbolAddress((void**)&pbd, g_bd);
    cudaGetSymbolAddress((void**)&pDhi, g_Dhi);
    cudaGetSymbolAddress((void**)&pDlo, g_Dlo);
    cudaGetSymbolAddress((void**)&pV, g_V);
    cudaGetSymbolAddress((void**)&pC, g_C);

    const int smem_plain = 3 * 2 * 128 * GP * sizeof(float);              // 36864
    const int smem_split = 3 * 4 * 128 * GP * sizeof(float);              // 73728
    const int smem_attn  = (3 * ASTG + 128 * PK) * sizeof(float) + 64;    // 194624
    static bool attr_set = false;
    if (!attr_set) {
        cudaFuncSetAttribute(gemm_split, cudaFuncAttributeMaxDynamicSharedMemorySize, smem_split);
        cudaFuncSetAttribute(gemm_plain<true>,  cudaFuncAttributeMaxDynamicSharedMemorySize, smem_plain);
        cudaFuncSetAttribute(gemm_plain<false>, cudaFuncAttributeMaxDynamicSharedMemorySize, smem_plain);
        cudaFuncSetAttribute(attn_mma, cudaFuncAttributeMaxDynamicSharedMemorySize, smem_attn);
        attr_set = true;
    }

    prep_x<<<MT*HH/256, 256>>>(x, bq, bk);
    prep_w<<<dim3(32, 32, 3), 256>>>(Wq, Wk, Wv, Wo);

    dim3 gg(HH/128, MT/128);  // (8, 32)
    gemm_split<<<gg, 256, smem_split>>>(pxhi, pxlo, pWdThi, pWdTlo, pbd, pDhi, pDlo);
    gemm_plain<true><<<gg, 256, smem_plain>>>(pxhi, pWvT, bv, pV);

    attn_mma<<<dim3(SS/128, BB*NHH), 512, smem_attn>>>();

    gemm_plain<false><<<gg, 256, smem_plain>>>(pC, pWoT, bo, out);
}